// round 10
// baseline (speedup 1.0000x reference)
#include <cuda_runtime.h>
#include <cstdint>

#define N_NODES 50000
#define C_DIM   128
#define E_EDGES 800000
#define NBUCK   65536
#define CANDMAX 2048
#define SCAN_BLOCKS ((N_NODES + 255) / 256)   // 196

typedef unsigned long long ull;

// ---------------- scratch (static device globals; no allocation) ----------------
__device__ float    g_deg[N_NODES];
__device__ float    g_dinv[N_NODES];
__device__ __align__(16) float g_agg[N_NODES * C_DIM];   // 25.6 MB
__device__ int      g_ecnt[N_NODES];
__device__ int      g_pref[N_NODES];                     // in-block exclusive prefix
__device__ int      g_bsum[SCAN_BLOCKS];
__device__ int      g_off[N_NODES + 1];
__device__ int      g_cur[N_NODES];
__device__ __align__(8) int2 g_csr[E_EDGES];             // (src, norm-as-int)
__device__ unsigned g_keys[N_NODES];
__device__ int      g_hist[NBUCK];
__device__ int      g_cnt;
__device__ int      g_thresh;
__device__ unsigned g_candk[CANDMAX];
__device__ int      g_candi[CANDMAX];
__device__ __align__(16) float g_Xt[C_DIM * C_DIM];
__device__ __align__(16) float g_gi[C_DIM * 3 * C_DIM];
__device__ __align__(16) float g_gh[C_DIM * 3 * C_DIM];
__device__ __align__(16) float g_Wnew[C_DIM * C_DIM];

// ---------------- side stream + events (created pre-main; no device memory) ----------------
struct HxSide {
    cudaStream_t s1;
    cudaEvent_t  evf, evj;
    HxSide() {
        cudaStreamCreateWithFlags(&s1, cudaStreamNonBlocking);
        cudaEventCreateWithFlags(&evf, cudaEventDisableTiming);
        cudaEventCreateWithFlags(&evj, cudaEventDisableTiming);
    }
};
static HxSide hx;

// ---------------- init ----------------
__global__ void k_init() {
    int i = blockIdx.x * blockDim.x + threadIdx.x;
    if (i < NBUCK)   g_hist[i] = 0;
    if (i < N_NODES) { g_deg[i] = 1.0f; g_ecnt[i] = 0; }
    if (i == 0)      g_cnt = 0;
}

// ---------------- degree (weight-sum) + edge-count histogram ----------------
__global__ void k_deg(const int* __restrict__ ei, const float* __restrict__ ew) {
    int e = blockIdx.x * 256 + threadIdx.x;
    if (e < E_EDGES) {
        int dst = ei[E_EDGES + e];
        atomicAdd(&g_deg[dst], ew[e]);
        atomicAdd(&g_ecnt[dst], 1);
    }
}

// ---------------- scan stage 1: per-block scan of counts + dinv ----------------
__global__ void k_scan1() {
    __shared__ int wsum[8];
    int i    = blockIdx.x * 256 + threadIdx.x;
    int lane = threadIdx.x & 31;
    int wid  = threadIdx.x >> 5;
    int v = (i < N_NODES) ? g_ecnt[i] : 0;
    int s = v;
    #pragma unroll
    for (int d = 1; d < 32; d <<= 1) {
        int t = __shfl_up_sync(0xffffffffu, s, d);
        if (lane >= d) s += t;
    }
    if (lane == 31) wsum[wid] = s;
    __syncthreads();
    if (wid == 0) {
        int ws = (lane < 8) ? wsum[lane] : 0;
        #pragma unroll
        for (int d = 1; d < 8; d <<= 1) {
            int t = __shfl_up_sync(0xffffffffu, ws, d);
            if (lane >= d) ws += t;
        }
        if (lane < 8) wsum[lane] = ws;
    }
    __syncthreads();
    int base = (wid > 0) ? wsum[wid - 1] : 0;
    if (i < N_NODES) {
        g_pref[i] = base + s - v;                 // exclusive in-block
        g_dinv[i] = rsqrtf(g_deg[i]);             // deg >= 1 always
    }
    if (threadIdx.x == 255) g_bsum[blockIdx.x] = base + s;
}

// ---------------- scan stage 2+3 fused: every block reduces its own prefix ----------------
__global__ void k_scan3() {
    __shared__ int sb[256];
    int t = threadIdx.x;
    sb[t] = (t < SCAN_BLOCKS && t < (int)blockIdx.x) ? g_bsum[t] : 0;
    __syncthreads();
    for (int s = 128; s > 0; s >>= 1) {
        if (t < s) sb[t] += sb[t + s];
        __syncthreads();
    }
    int boff = sb[0];
    int i = blockIdx.x * 256 + t;
    if (i < N_NODES) {
        int o = g_pref[i] + boff;
        g_off[i] = o;
        g_cur[i] = o;
    }
    if (blockIdx.x == 0 && t == 0) g_off[N_NODES] = E_EDGES;
}

// ---------------- fill CSR: (src, precomputed norm) grouped by dst ----------------
__global__ void k_fill(const int* __restrict__ ei, const float* __restrict__ ew) {
    int e = blockIdx.x * 256 + threadIdx.x;
    if (e >= E_EDGES) return;
    int src = ei[e];
    int dst = ei[E_EDGES + e];
    float nrm = g_dinv[src] * ew[e] * g_dinv[dst];
    int pos = atomicAdd(&g_cur[dst], 1);
    g_csr[pos] = make_int2(src, __float_as_int(nrm));
}

// ---------------- atomic-free aggregation: warp per node ----------------
__global__ void k_agg(const float* __restrict__ X) {
    int gt   = blockIdx.x * blockDim.x + threadIdx.x;
    int w    = gt >> 5;
    int lane = gt & 31;
    if (w >= N_NODES) return;
    int beg = g_off[w], end = g_off[w + 1];
    float di = g_dinv[w];
    float s  = di * di;                              // self-loop term
    float4 x = ((const float4*)X)[w * 32 + lane];
    float4 acc = make_float4(x.x * s, x.y * s, x.z * s, x.w * s);
    for (int e = beg; e < end; e++) {
        int2 c = g_csr[e];                           // warp-uniform broadcast load
        float nrm = __int_as_float(c.y);
        float4 xs = ((const float4*)X)[c.x * 32 + lane];
        acc.x += xs.x * nrm; acc.y += xs.y * nrm;
        acc.z += xs.z * nrm; acc.w += xs.w * nrm;
    }
    ((float4*)g_agg)[w * 32 + lane] = acc;
}

// ---------------- scores + key histogram (warp per node, pnorm fused) ----------------
__global__ void k_score(const float* __restrict__ X, const float* __restrict__ p) {
    __shared__ float4 ps[32];
    __shared__ float spinv;
    if (threadIdx.x < 32) {
        float4 q = ((const float4*)p)[threadIdx.x];
        ps[threadIdx.x] = q;
        float ss = q.x * q.x + q.y * q.y + q.z * q.z + q.w * q.w;
        #pragma unroll
        for (int o = 16; o; o >>= 1) ss += __shfl_xor_sync(0xffffffffu, ss, o);
        if (threadIdx.x == 0) spinv = rsqrtf(ss);
    }
    __syncthreads();
    int w    = (blockIdx.x * blockDim.x + threadIdx.x) >> 5;
    int lane = threadIdx.x & 31;
    if (w >= N_NODES) return;
    float4 x  = ((const float4*)X)[w * 32 + lane];
    float4 pp = ps[lane];
    float d = x.x * pp.x + x.y * pp.y + x.z * pp.z + x.w * pp.w;
    for (int o = 16; o; o >>= 1) d += __shfl_xor_sync(0xffffffffu, d, o);
    if (lane == 0) {
        float s = d * spinv;
        unsigned bits = __float_as_uint(s);
        unsigned key  = (bits & 0x80000000u) ? ~bits : (bits ^ 0x80000000u);
        g_keys[w] = key;
        atomicAdd(&g_hist[key >> 16], 1);
    }
}

// ---------------- threshold bucket ----------------
__global__ void k_thresh() {
    __shared__ int csum[1024];
    int t = threadIdx.x;
    int s = 0;
    int base = t * 64;
    for (int b = 0; b < 64; b++) s += g_hist[base + b];
    csum[t] = s;
    __syncthreads();
    if (t == 0) {
        int cum = 0, chunk = 0;
        for (int c = 1023; c >= 0; c--) {
            if (cum + csum[c] >= C_DIM) { chunk = c; break; }
            cum += csum[c];
        }
        int B = chunk * 64;
        for (int b = chunk * 64 + 63; b >= chunk * 64; b--) {
            cum += g_hist[b];
            if (cum >= C_DIM) { B = b; break; }
        }
        g_thresh = B;
    }
}

// ---------------- compact candidates ----------------
__global__ void k_compact() {
    int i = blockIdx.x * 256 + threadIdx.x;
    if (i >= N_NODES) return;
    unsigned key = g_keys[i];
    if ((int)(key >> 16) >= g_thresh) {
        int pos = atomicAdd(&g_cnt, 1);
        if (pos < CANDMAX) { g_candk[pos] = key; g_candi[pos] = i; }
    }
}

// ---------------- exact top-128 sort + X_tilde ----------------
__global__ void k_topk(const float* __restrict__ X) {
    __shared__ unsigned long long s[CANDMAX];
    __shared__ int   sidx[C_DIM];
    __shared__ float sgate[C_DIM];
    int t = threadIdx.x;
    int cnt = g_cnt; if (cnt > CANDMAX) cnt = CANDMAX;
    for (int i = t; i < CANDMAX; i += 256) {
        if (i < cnt)
            s[i] = ((unsigned long long)g_candk[i] << 32) |
                   (unsigned)(0xFFFFFFFFu - (unsigned)g_candi[i]);
        else
            s[i] = 0ull;
    }
    __syncthreads();
    for (int k2 = 2; k2 <= CANDMAX; k2 <<= 1)
        for (int j = k2 >> 1; j > 0; j >>= 1) {
            for (int i = t; i < CANDMAX; i += 256) {
                int ixj = i ^ j;
                if (ixj > i) {
                    unsigned long long a = s[i], b = s[ixj];
                    bool asc = ((i & k2) == 0);
                    if (asc ? (a > b) : (a < b)) { s[i] = b; s[ixj] = a; }
                }
            }
            __syncthreads();
        }
    if (t < C_DIM) {
        unsigned long long comp = s[CANDMAX - 1 - t];
        unsigned key = (unsigned)(comp >> 32);
        int idx = (int)(0xFFFFFFFFu - (unsigned)comp);
        unsigned bits = (key & 0x80000000u) ? (key ^ 0x80000000u) : ~key;
        sidx[t]  = idx;
        sgate[t] = tanhf(__uint_as_float(bits));
    }
    __syncthreads();
    for (int i = t; i < C_DIM * C_DIM; i += 256) {
        int r = i >> 7, c = i & 127;
        g_Xt[i] = X[sidx[r] * C_DIM + c] * sgate[r];
    }
}

// ---------------- merged GRU GEMMs: z=0: gi = Xt@W_ih^T ; z=1: gh = Wc@W_hh^T ----------------
__global__ void __launch_bounds__(256)
k_gemm(const float* __restrict__ Wc, const float* __restrict__ Wih,
       const float* __restrict__ Whh) {
    int mode = blockIdx.z;
    const float* A = (mode == 0) ? g_Xt : Wc;
    const float* B = (mode == 0) ? Wih  : Whh;
    float* Cm      = (mode == 0) ? g_gi : g_gh;
    const int M = C_DIM, Nn = 3 * C_DIM;

    extern __shared__ float sm[];
    float* Bs = sm;                 // [128][129]
    float* As = sm + 128 * 129;     // [64][128]
    int tid = threadIdx.x;
    int bx = blockIdx.x, by = blockIdx.y;

    #pragma unroll 4
    for (int it = 0; it < 64; it++) {
        int flat = tid + it * 256;
        int n = flat >> 7, k = flat & 127;
        Bs[n * 129 + k] = B[(by * 128 + n) * C_DIM + k];
    }
    int row0 = bx * 64;
    #pragma unroll 4
    for (int it = 0; it < 32; it++) {
        int flat = tid + it * 256;
        int r = flat >> 7, k = flat & 127;
        As[flat] = A[(row0 + r) * C_DIM + k];
    }
    __syncthreads();

    int tx = tid & 31, ty = tid >> 5;
    float acc[8][4];
    #pragma unroll
    for (int i = 0; i < 8; i++)
        #pragma unroll
        for (int j = 0; j < 4; j++) acc[i][j] = 0.0f;

    const float* Ap = As + ty * 8 * 128;
    const float* Bp = Bs + tx * 129;
    #pragma unroll 2
    for (int k4 = 0; k4 < 32; k4++) {
        float4 a4[8];
        #pragma unroll
        for (int i = 0; i < 8; i++)
            a4[i] = *(const float4*)(Ap + i * 128 + k4 * 4);
        #pragma unroll
        for (int j = 0; j < 4; j++) {
            const float* bp = Bp + j * (32 * 129) + k4 * 4;
            float b0 = bp[0], b1 = bp[1], b2 = bp[2], b3 = bp[3];
            #pragma unroll
            for (int i = 0; i < 8; i++)
                acc[i][j] += a4[i].x * b0 + a4[i].y * b1 + a4[i].z * b2 + a4[i].w * b3;
        }
    }
    #pragma unroll
    for (int i = 0; i < 8; i++) {
        int gr = row0 + ty * 8 + i;
        #pragma unroll
        for (int j = 0; j < 4; j++)
            Cm[gr * Nn + by * 128 + tx + 32 * j] = acc[i][j];
    }
    (void)M;
}

// ---------------- GRU gates -> W_new ----------------
__global__ void k_gates(const float* __restrict__ b_ih, const float* __restrict__ b_hh,
                        const float* __restrict__ Wc) {
    int i = blockIdx.x * 256 + threadIdx.x;
    if (i >= C_DIM * C_DIM) return;
    int b = i >> 7, j = i & 127;
    float gir = g_gi[b * 384 + j]       + b_ih[j];
    float ghr = g_gh[b * 384 + j]       + b_hh[j];
    float giz = g_gi[b * 384 + 128 + j] + b_ih[128 + j];
    float ghz = g_gh[b * 384 + 128 + j] + b_hh[128 + j];
    float gin = g_gi[b * 384 + 256 + j] + b_ih[256 + j];
    float ghn = g_gh[b * 384 + 256 + j] + b_hh[256 + j];
    float r = 1.0f / (1.0f + expf(-(gir + ghr)));
    float z = 1.0f / (1.0f + expf(-(giz + ghz)));
    float n = tanhf(gin + r * ghn);
    g_Wnew[i] = (1.0f - z) * n + z * Wc[i];
}

// ---------------- final GEMM with packed fma.rn.f32x2 ----------------
// out[m,n] = sum_k agg[m,k]*Wnew[n,k] + bias[n]
__global__ void __launch_bounds__(256)
k_gemm2(float* __restrict__ out, const float* __restrict__ bias) {
    extern __shared__ float sm2[];
    float* Ast = sm2;                  // [128][68]
    float* Bst = sm2 + 128 * 68;       // [128][65]
    int tid = threadIdx.x;
    int row0 = blockIdx.x * 64;
    int col0 = blockIdx.y * 64;

    #pragma unroll 4
    for (int it = 0; it < 32; it++) {               // B: Wnew[col0+n][k] -> Bst[k][n]
        int flat = tid + it * 256;
        int k = flat & 127, n = flat >> 7;
        Bst[k * 65 + n] = g_Wnew[(col0 + n) * C_DIM + k];
    }
    #pragma unroll 4
    for (int it = 0; it < 32; it++) {               // A: agg[row0+r][k] -> Ast[k][r]
        int flat = tid + it * 256;
        int k = flat & 127, r = flat >> 7;
        int gr = row0 + r;
        Ast[k * 68 + r] = (gr < N_NODES) ? g_agg[gr * C_DIM + k] : 0.0f;
    }
    __syncthreads();

    int tx = tid & 31, ty = tid >> 5;
    int m0 = ty * 8;
    ull acc[4][2];
    #pragma unroll
    for (int i = 0; i < 4; i++) { acc[i][0] = 0ull; acc[i][1] = 0ull; }

    #pragma unroll 4
    for (int k = 0; k < 128; k++) {
        double2 ad0 = *(const double2*)(Ast + k * 68 + m0);
        double2 ad1 = *(const double2*)(Ast + k * 68 + m0 + 4);
        ull a[4];
        a[0] = __double_as_longlong(ad0.x);
        a[1] = __double_as_longlong(ad0.y);
        a[2] = __double_as_longlong(ad1.x);
        a[3] = __double_as_longlong(ad1.y);
        float b0 = Bst[k * 65 + tx];
        float b1 = Bst[k * 65 + tx + 32];
        ull bb0, bb1;
        asm("mov.b64 %0, {%1, %1};" : "=l"(bb0) : "f"(b0));
        asm("mov.b64 %0, {%1, %1};" : "=l"(bb1) : "f"(b1));
        #pragma unroll
        for (int i = 0; i < 4; i++) {
            asm("fma.rn.f32x2 %0, %1, %2, %0;" : "+l"(acc[i][0]) : "l"(a[i]), "l"(bb0));
            asm("fma.rn.f32x2 %0, %1, %2, %0;" : "+l"(acc[i][1]) : "l"(a[i]), "l"(bb1));
        }
    }

    float bv0 = bias[col0 + tx];
    float bv1 = bias[col0 + tx + 32];
    #pragma unroll
    for (int i = 0; i < 4; i++) {
        float c0lo, c0hi, c1lo, c1hi;
        asm("mov.b64 {%0, %1}, %2;" : "=f"(c0lo), "=f"(c0hi) : "l"(acc[i][0]));
        asm("mov.b64 {%0, %1}, %2;" : "=f"(c1lo), "=f"(c1hi) : "l"(acc[i][1]));
        int gr0 = row0 + m0 + 2 * i;
        int gr1 = gr0 + 1;
        if (gr0 < N_NODES) {
            out[gr0 * C_DIM + col0 + tx]      = c0lo + bv0;
            out[gr0 * C_DIM + col0 + tx + 32] = c1lo + bv1;
        }
        if (gr1 < N_NODES) {
            out[gr1 * C_DIM + col0 + tx]      = c0hi + bv0;
            out[gr1 * C_DIM + col0 + tx + 32] = c1hi + bv1;
        }
    }
}

// ---------------- launch ----------------
extern "C" void kernel_launch(void* const* d_in, const int* in_sizes, int n_in,
                              void* d_out, int out_size) {
    const float* X      = (const float*)d_in[0];
    const float* ew     = (const float*)d_in[1];
    const float* p      = (const float*)d_in[2];
    const float* W_ih   = (const float*)d_in[3];
    const float* W_hh   = (const float*)d_in[4];
    const float* b_ih   = (const float*)d_in[5];
    const float* b_hh   = (const float*)d_in[6];
    const float* W_conv = (const float*)d_in[7];
    const float* b_conv = (const float*)d_in[8];
    const int*   ei     = (const int*)d_in[9];     // int32 (JAX x64 disabled)
    float* out = (float*)d_out;

    const int GEMM_SMEM  = (128 * 129 + 64 * 128) * sizeof(float);   // 98816 B
    const int GEMM2_SMEM = (128 * 68 + 128 * 65) * sizeof(float);    // 68096 B
    cudaFuncSetAttribute(k_gemm,  cudaFuncAttributeMaxDynamicSharedMemorySize, GEMM_SMEM);
    cudaFuncSetAttribute(k_gemm2, cudaFuncAttributeMaxDynamicSharedMemorySize, GEMM2_SMEM);

    // common init (hist zero + deg/ecnt/cnt)
    k_init<<<256, 256>>>();

    // ---- fork: chain B (topk/GRU) on side stream ----
    cudaEventRecord(hx.evf, 0);
    cudaStreamWaitEvent(hx.s1, hx.evf, 0);

    k_score  <<<(N_NODES + 7) / 8, 256, 0, hx.s1>>>(X, p);
    k_thresh <<<1, 1024, 0, hx.s1>>>();
    k_compact<<<(N_NODES + 255) / 256, 256, 0, hx.s1>>>();
    k_topk   <<<1, 256, 0, hx.s1>>>(X);
    k_gemm   <<<dim3(2, 3, 2), 256, GEMM_SMEM, hx.s1>>>(W_conv, W_ih, W_hh);
    k_gates  <<<64, 256, 0, hx.s1>>>(b_ih, b_hh, W_conv);
    cudaEventRecord(hx.evj, hx.s1);

    // ---- chain A (edge/agg) on main stream ----
    k_deg  <<<(E_EDGES + 255) / 256, 256>>>(ei, ew);
    k_scan1<<<SCAN_BLOCKS, 256>>>();
    k_scan3<<<SCAN_BLOCKS, 256>>>();
    k_fill <<<(E_EDGES + 255) / 256, 256>>>(ei, ew);
    k_agg  <<<(N_NODES * 32 + 255) / 256, 256>>>(X);

    // ---- join, then final GEMM ----
    cudaStreamWaitEvent(0, hx.evj, 0);
    k_gemm2<<<dim3((N_NODES + 63) / 64, 2), 256, GEMM2_SMEM>>>(out, b_conv);
}

// round 11
// speedup vs baseline: 1.0353x; 1.0353x over previous
#include <cuda_runtime.h>
#include <cstdint>

#define N_NODES 50000
#define C_DIM   128
#define E_EDGES 800000
#define NBUCK   65536
#define CANDMAX 2048
#define SCAN_BLOCKS ((N_NODES + 255) / 256)   // 196

typedef unsigned long long ull;

// ---------------- scratch (static device globals; no allocation) ----------------
__device__ ull      g_degp[N_NODES];                     // packed: cnt<<52 | wsum(32.32)
__device__ float    g_dinv[N_NODES];
__device__ __align__(16) float g_agg[N_NODES * C_DIM];   // 25.6 MB
__device__ int      g_pref[N_NODES];                     // in-block exclusive prefix
__device__ int      g_bsum[SCAN_BLOCKS];
__device__ int      g_off[N_NODES + 1];
__device__ int      g_cur[N_NODES];
__device__ __align__(8) int2 g_csr[E_EDGES];             // (src, dinv[src]*w as int)
__device__ unsigned g_keys[N_NODES];
__device__ int      g_hist[NBUCK];
__device__ int      g_cnt;
__device__ int      g_thresh;
__device__ unsigned g_candk[CANDMAX];
__device__ int      g_candi[CANDMAX];
__device__ __align__(16) float g_Xt[C_DIM * C_DIM];
__device__ __align__(16) float g_gi[C_DIM * 3 * C_DIM];
__device__ __align__(16) float g_gh[C_DIM * 3 * C_DIM];
__device__ __align__(16) float g_Wnew[C_DIM * C_DIM];

// ---------------- side stream + events (created pre-main; no device memory) ----------------
struct HxSide {
    cudaStream_t s1;
    cudaEvent_t  evf, evj;
    HxSide() {
        cudaStreamCreateWithFlags(&s1, cudaStreamNonBlocking);
        cudaEventCreateWithFlags(&evf, cudaEventDisableTiming);
        cudaEventCreateWithFlags(&evj, cudaEventDisableTiming);
    }
};
static HxSide hx;

// ---------------- init ----------------
__global__ void k_init() {
    int i = blockIdx.x * blockDim.x + threadIdx.x;
    if (i < NBUCK)   g_hist[i] = 0;
    if (i < N_NODES) g_degp[i] = (1ull << 32);   // self-loop weight 1.0, count 0
    if (i == 0)      g_cnt = 0;
}

// ---------------- degree: ONE packed 64-bit atomic per edge ----------------
__global__ void k_deg(const int* __restrict__ ei, const float* __restrict__ ew) {
    int e = blockIdx.x * 256 + threadIdx.x;
    if (e < E_EDGES) {
        int dst = ei[E_EDGES + e];
        ull v = (ull)(ew[e] * 4294967296.0f) + (1ull << 52);
        atomicAdd(&g_degp[dst], v);
    }
}

// ---------------- scan stage 1: per-block scan of counts + dinv ----------------
__global__ void k_scan1() {
    __shared__ int wsum[8];
    int i    = blockIdx.x * 256 + threadIdx.x;
    int lane = threadIdx.x & 31;
    int wid  = threadIdx.x >> 5;
    int v = 0;
    if (i < N_NODES) {
        ull d = g_degp[i];
        v = (int)(d >> 52);
        float w = __ull2float_rn(d & ((1ull << 52) - 1ull)) * (1.0f / 4294967296.0f);
        g_dinv[i] = rsqrtf(w);                    // w >= 1 always
    }
    int s = v;
    #pragma unroll
    for (int d = 1; d < 32; d <<= 1) {
        int t = __shfl_up_sync(0xffffffffu, s, d);
        if (lane >= d) s += t;
    }
    if (lane == 31) wsum[wid] = s;
    __syncthreads();
    if (wid == 0) {
        int ws = (lane < 8) ? wsum[lane] : 0;
        #pragma unroll
        for (int d = 1; d < 8; d <<= 1) {
            int t = __shfl_up_sync(0xffffffffu, ws, d);
            if (lane >= d) ws += t;
        }
        if (lane < 8) wsum[lane] = ws;
    }
    __syncthreads();
    int base = (wid > 0) ? wsum[wid - 1] : 0;
    if (i < N_NODES) g_pref[i] = base + s - v;    // exclusive in-block
    if (threadIdx.x == 255) g_bsum[blockIdx.x] = base + s;
}

// ---------------- scan stage 2+3 fused: every block reduces its own prefix ----------------
__global__ void k_scan3() {
    __shared__ int sb[256];
    int t = threadIdx.x;
    sb[t] = (t < SCAN_BLOCKS && t < (int)blockIdx.x) ? g_bsum[t] : 0;
    __syncthreads();
    for (int s = 128; s > 0; s >>= 1) {
        if (t < s) sb[t] += sb[t + s];
        __syncthreads();
    }
    int boff = sb[0];
    int i = blockIdx.x * 256 + t;
    if (i < N_NODES) {
        int o = g_pref[i] + boff;
        g_off[i] = o;
        g_cur[i] = o;
    }
    if (blockIdx.x == 0 && t == 0) g_off[N_NODES] = E_EDGES;
}

// ---------------- fill CSR: (src, dinv[src]*w) grouped by dst ----------------
__global__ void k_fill(const int* __restrict__ ei, const float* __restrict__ ew) {
    int e = blockIdx.x * 256 + threadIdx.x;
    if (e >= E_EDGES) return;
    int src = ei[e];
    int dst = ei[E_EDGES + e];
    float s = g_dinv[src] * ew[e];                // dinv[dst] folded into k_agg
    int pos = atomicAdd(&g_cur[dst], 1);
    g_csr[pos] = make_int2(src, __float_as_int(s));
}

// ---------------- atomic-free aggregation: warp per node ----------------
__global__ void k_agg(const float* __restrict__ X) {
    int gt   = blockIdx.x * blockDim.x + threadIdx.x;
    int w    = gt >> 5;
    int lane = gt & 31;
    if (w >= N_NODES) return;
    int beg = g_off[w], end = g_off[w + 1];
    float di = g_dinv[w];
    float4 x = ((const float4*)X)[w * 32 + lane];
    float4 acc = make_float4(x.x * di, x.y * di, x.z * di, x.w * di);  // self-loop: di*x
    for (int e = beg; e < end; e++) {
        int2 c = g_csr[e];                        // warp-uniform broadcast load
        float s = __int_as_float(c.y);
        float4 xs = ((const float4*)X)[c.x * 32 + lane];
        acc.x += xs.x * s; acc.y += xs.y * s;
        acc.z += xs.z * s; acc.w += xs.w * s;
    }
    acc.x *= di; acc.y *= di; acc.z *= di; acc.w *= di;  // outer dinv[dst]
    ((float4*)g_agg)[w * 32 + lane] = acc;
}

// ---------------- scores + key histogram (warp per node, pnorm fused) ----------------
__global__ void k_score(const float* __restrict__ X, const float* __restrict__ p) {
    __shared__ float4 ps[32];
    __shared__ float spinv;
    if (threadIdx.x < 32) {
        float4 q = ((const float4*)p)[threadIdx.x];
        ps[threadIdx.x] = q;
        float ss = q.x * q.x + q.y * q.y + q.z * q.z + q.w * q.w;
        #pragma unroll
        for (int o = 16; o; o >>= 1) ss += __shfl_xor_sync(0xffffffffu, ss, o);
        if (threadIdx.x == 0) spinv = rsqrtf(ss);
    }
    __syncthreads();
    int w    = (blockIdx.x * blockDim.x + threadIdx.x) >> 5;
    int lane = threadIdx.x & 31;
    if (w >= N_NODES) return;
    float4 x  = ((const float4*)X)[w * 32 + lane];
    float4 pp = ps[lane];
    float d = x.x * pp.x + x.y * pp.y + x.z * pp.z + x.w * pp.w;
    for (int o = 16; o; o >>= 1) d += __shfl_xor_sync(0xffffffffu, d, o);
    if (lane == 0) {
        float s = d * spinv;
        unsigned bits = __float_as_uint(s);
        unsigned key  = (bits & 0x80000000u) ? ~bits : (bits ^ 0x80000000u);
        g_keys[w] = key;
        atomicAdd(&g_hist[key >> 16], 1);
    }
}

// ---------------- threshold bucket ----------------
__global__ void k_thresh() {
    __shared__ int csum[1024];
    int t = threadIdx.x;
    int s = 0;
    int base = t * 64;
    for (int b = 0; b < 64; b++) s += g_hist[base + b];
    csum[t] = s;
    __syncthreads();
    if (t == 0) {
        int cum = 0, chunk = 0;
        for (int c = 1023; c >= 0; c--) {
            if (cum + csum[c] >= C_DIM) { chunk = c; break; }
            cum += csum[c];
        }
        int B = chunk * 64;
        for (int b = chunk * 64 + 63; b >= chunk * 64; b--) {
            cum += g_hist[b];
            if (cum >= C_DIM) { B = b; break; }
        }
        g_thresh = B;
    }
}

// ---------------- compact candidates ----------------
__global__ void k_compact() {
    int i = blockIdx.x * 256 + threadIdx.x;
    if (i >= N_NODES) return;
    unsigned key = g_keys[i];
    if ((int)(key >> 16) >= g_thresh) {
        int pos = atomicAdd(&g_cnt, 1);
        if (pos < CANDMAX) { g_candk[pos] = key; g_candi[pos] = i; }
    }
}

// ---------------- exact top-128 sort + X_tilde ----------------
__global__ void k_topk(const float* __restrict__ X) {
    __shared__ unsigned long long s[CANDMAX];
    __shared__ int   sidx[C_DIM];
    __shared__ float sgate[C_DIM];
    int t = threadIdx.x;
    int cnt = g_cnt; if (cnt > CANDMAX) cnt = CANDMAX;
    for (int i = t; i < CANDMAX; i += 256) {
        if (i < cnt)
            s[i] = ((unsigned long long)g_candk[i] << 32) |
                   (unsigned)(0xFFFFFFFFu - (unsigned)g_candi[i]);
        else
            s[i] = 0ull;
    }
    __syncthreads();
    for (int k2 = 2; k2 <= CANDMAX; k2 <<= 1)
        for (int j = k2 >> 1; j > 0; j >>= 1) {
            for (int i = t; i < CANDMAX; i += 256) {
                int ixj = i ^ j;
                if (ixj > i) {
                    unsigned long long a = s[i], b = s[ixj];
                    bool asc = ((i & k2) == 0);
                    if (asc ? (a > b) : (a < b)) { s[i] = b; s[ixj] = a; }
                }
            }
            __syncthreads();
        }
    if (t < C_DIM) {
        unsigned long long comp = s[CANDMAX - 1 - t];
        unsigned key = (unsigned)(comp >> 32);
        int idx = (int)(0xFFFFFFFFu - (unsigned)comp);
        unsigned bits = (key & 0x80000000u) ? (key ^ 0x80000000u) : ~key;
        sidx[t]  = idx;
        sgate[t] = tanhf(__uint_as_float(bits));
    }
    __syncthreads();
    for (int i = t; i < C_DIM * C_DIM; i += 256) {
        int r = i >> 7, c = i & 127;
        g_Xt[i] = X[sidx[r] * C_DIM + c] * sgate[r];
    }
}

// ---------------- merged GRU GEMMs: z=0: gi = Xt@W_ih^T ; z=1: gh = Wc@W_hh^T ----------------
__global__ void __launch_bounds__(256)
k_gemm(const float* __restrict__ Wc, const float* __restrict__ Wih,
       const float* __restrict__ Whh) {
    int mode = blockIdx.z;
    const float* A = (mode == 0) ? g_Xt : Wc;
    const float* B = (mode == 0) ? Wih  : Whh;
    float* Cm      = (mode == 0) ? g_gi : g_gh;
    const int Nn = 3 * C_DIM;

    extern __shared__ float sm[];
    float* Bs = sm;                 // [128][129]
    float* As = sm + 128 * 129;     // [64][128]
    int tid = threadIdx.x;
    int bx = blockIdx.x, by = blockIdx.y;

    #pragma unroll 4
    for (int it = 0; it < 64; it++) {
        int flat = tid + it * 256;
        int n = flat >> 7, k = flat & 127;
        Bs[n * 129 + k] = B[(by * 128 + n) * C_DIM + k];
    }
    int row0 = bx * 64;
    #pragma unroll 4
    for (int it = 0; it < 32; it++) {
        int flat = tid + it * 256;
        int r = flat >> 7, k = flat & 127;
        As[flat] = A[(row0 + r) * C_DIM + k];
    }
    __syncthreads();

    int tx = tid & 31, ty = tid >> 5;
    float acc[8][4];
    #pragma unroll
    for (int i = 0; i < 8; i++)
        #pragma unroll
        for (int j = 0; j < 4; j++) acc[i][j] = 0.0f;

    const float* Ap = As + ty * 8 * 128;
    const float* Bp = Bs + tx * 129;
    #pragma unroll 2
    for (int k4 = 0; k4 < 32; k4++) {
        float4 a4[8];
        #pragma unroll
        for (int i = 0; i < 8; i++)
            a4[i] = *(const float4*)(Ap + i * 128 + k4 * 4);
        #pragma unroll
        for (int j = 0; j < 4; j++) {
            const float* bp = Bp + j * (32 * 129) + k4 * 4;
            float b0 = bp[0], b1 = bp[1], b2 = bp[2], b3 = bp[3];
            #pragma unroll
            for (int i = 0; i < 8; i++)
                acc[i][j] += a4[i].x * b0 + a4[i].y * b1 + a4[i].z * b2 + a4[i].w * b3;
        }
    }
    #pragma unroll
    for (int i = 0; i < 8; i++) {
        int gr = row0 + ty * 8 + i;
        #pragma unroll
        for (int j = 0; j < 4; j++)
            Cm[gr * Nn + by * 128 + tx + 32 * j] = acc[i][j];
    }
}

// ---------------- GRU gates -> W_new ----------------
__global__ void k_gates(const float* __restrict__ b_ih, const float* __restrict__ b_hh,
                        const float* __restrict__ Wc) {
    int i = blockIdx.x * 256 + threadIdx.x;
    if (i >= C_DIM * C_DIM) return;
    int b = i >> 7, j = i & 127;
    float gir = g_gi[b * 384 + j]       + b_ih[j];
    float ghr = g_gh[b * 384 + j]       + b_hh[j];
    float giz = g_gi[b * 384 + 128 + j] + b_ih[128 + j];
    float ghz = g_gh[b * 384 + 128 + j] + b_hh[128 + j];
    float gin = g_gi[b * 384 + 256 + j] + b_ih[256 + j];
    float ghn = g_gh[b * 384 + 256 + j] + b_hh[256 + j];
    float r = 1.0f / (1.0f + expf(-(gir + ghr)));
    float z = 1.0f / (1.0f + expf(-(giz + ghz)));
    float n = tanhf(gin + r * ghn);
    g_Wnew[i] = (1.0f - z) * n + z * Wc[i];
}

// ---------------- final GEMM, BN=128 full-width, packed fma.rn.f32x2 ----------------
// out[m,n] = sum_k agg[m,k]*Wnew[n,k] + bias[n]
__global__ void __launch_bounds__(256, 2)
k_gemm2(float* __restrict__ out, const float* __restrict__ bias) {
    extern __shared__ float sm2[];
    float* Ast = sm2;                  // [128 k][68 m]
    float* Bst = sm2 + 128 * 68;       // [128 k][130 n]
    int tid = threadIdx.x;
    int row0 = blockIdx.x * 64;

    #pragma unroll 8
    for (int it = 0; it < 64; it++) {               // B: Wnew[n][k] -> Bst[k][n]
        int flat = tid + it * 256;
        int k = flat & 127, n = flat >> 7;
        Bst[k * 130 + n] = g_Wnew[n * C_DIM + k];
    }
    #pragma unroll 4
    for (int it = 0; it < 32; it++) {               // A: agg[row0+r][k] -> Ast[k][r]
        int flat = tid + it * 256;
        int k = flat & 127, r = flat >> 7;
        int gr = row0 + r;
        Ast[k * 68 + r] = (gr < N_NODES) ? g_agg[gr * C_DIM + k] : 0.0f;
    }
    __syncthreads();

    int tx = tid & 31, ty = tid >> 5;
    int m0 = ty * 8;
    ull acc[4][4];
    #pragma unroll
    for (int i = 0; i < 4; i++)
        #pragma unroll
        for (int j = 0; j < 4; j++) acc[i][j] = 0ull;

    #pragma unroll 2
    for (int k = 0; k < 128; k++) {
        double2 ad0 = *(const double2*)(Ast + k * 68 + m0);      // rows m0..m0+3
        double2 ad1 = *(const double2*)(Ast + k * 68 + m0 + 4);  // rows m0+4..m0+7
        ull a[4];
        a[0] = __double_as_longlong(ad0.x);
        a[1] = __double_as_longlong(ad0.y);
        a[2] = __double_as_longlong(ad1.x);
        a[3] = __double_as_longlong(ad1.y);
        ull bb[4];
        #pragma unroll
        for (int j = 0; j < 4; j++) {
            float b = Bst[k * 130 + tx + 32 * j];
            asm("mov.b64 %0, {%1, %1};" : "=l"(bb[j]) : "f"(b));
        }
        #pragma unroll
        for (int i = 0; i < 4; i++)
            #pragma unroll
            for (int j = 0; j < 4; j++)
                asm("fma.rn.f32x2 %0, %1, %2, %0;" : "+l"(acc[i][j]) : "l"(a[i]), "l"(bb[j]));
    }

    float bv[4];
    #pragma unroll
    for (int j = 0; j < 4; j++) bv[j] = bias[tx + 32 * j];
    #pragma unroll
    for (int i = 0; i < 4; i++) {
        int gr0 = row0 + m0 + 2 * i;
        int gr1 = gr0 + 1;
        #pragma unroll
        for (int j = 0; j < 4; j++) {
            float clo, chi;
            asm("mov.b64 {%0, %1}, %2;" : "=f"(clo), "=f"(chi) : "l"(acc[i][j]));
            if (gr0 < N_NODES) out[gr0 * C_DIM + tx + 32 * j] = clo + bv[j];
            if (gr1 < N_NODES) out[gr1 * C_DIM + tx + 32 * j] = chi + bv[j];
        }
    }
}

// ---------------- launch ----------------
extern "C" void kernel_launch(void* const* d_in, const int* in_sizes, int n_in,
                              void* d_out, int out_size) {
    const float* X      = (const float*)d_in[0];
    const float* ew     = (const float*)d_in[1];
    const float* p      = (const float*)d_in[2];
    const float* W_ih   = (const float*)d_in[3];
    const float* W_hh   = (const float*)d_in[4];
    const float* b_ih   = (const float*)d_in[5];
    const float* b_hh   = (const float*)d_in[6];
    const float* W_conv = (const float*)d_in[7];
    const float* b_conv = (const float*)d_in[8];
    const int*   ei     = (const int*)d_in[9];     // int32 (JAX x64 disabled)
    float* out = (float*)d_out;

    const int GEMM_SMEM  = (128 * 129 + 64 * 128) * sizeof(float);   // 98816 B
    const int GEMM2_SMEM = (128 * 68 + 128 * 130) * sizeof(float);   // 101376 B
    cudaFuncSetAttribute(k_gemm,  cudaFuncAttributeMaxDynamicSharedMemorySize, GEMM_SMEM);
    cudaFuncSetAttribute(k_gemm2, cudaFuncAttributeMaxDynamicSharedMemorySize, GEMM2_SMEM);

    // common init (hist zero + packed deg + cnt)
    k_init<<<256, 256>>>();

    // ---- fork: chain B (topk/GRU) on side stream ----
    cudaEventRecord(hx.evf, 0);
    cudaStreamWaitEvent(hx.s1, hx.evf, 0);

    k_score  <<<(N_NODES + 7) / 8, 256, 0, hx.s1>>>(X, p);
    k_thresh <<<1, 1024, 0, hx.s1>>>();
    k_compact<<<(N_NODES + 255) / 256, 256, 0, hx.s1>>>();
    k_topk   <<<1, 256, 0, hx.s1>>>(X);
    k_gemm   <<<dim3(2, 3, 2), 256, GEMM_SMEM, hx.s1>>>(W_conv, W_ih, W_hh);
    k_gates  <<<64, 256, 0, hx.s1>>>(b_ih, b_hh, W_conv);
    cudaEventRecord(hx.evj, hx.s1);

    // ---- chain A (edge/agg) on main stream ----
    k_deg  <<<(E_EDGES + 255) / 256, 256>>>(ei, ew);
    k_scan1<<<SCAN_BLOCKS, 256>>>();
    k_scan3<<<SCAN_BLOCKS, 256>>>();
    k_fill <<<(E_EDGES + 255) / 256, 256>>>(ei, ew);
    k_agg  <<<(N_NODES * 32 + 255) / 256, 256>>>(X);

    // ---- join, then final GEMM ----
    cudaStreamWaitEvent(0, hx.evj, 0);
    k_gemm2<<<(N_NODES + 63) / 64, 256, GEMM2_SMEM>>>(out, b_conv);
}

// round 12
// speedup vs baseline: 1.1202x; 1.0820x over previous
#include <cuda_runtime.h>
#include <cstdint>

#define N_NODES 50000
#define C_DIM   128
#define E_EDGES 800000
#define NBUCK   65536
#define CANDMAX 2048
#define BCAP    64         // bucket capacity per node (E[deg]=16, P(>=64)~1e-18)
#define OVMAX   4096       // overflow safety net

typedef unsigned long long ull;

// ---------------- scratch (static device globals; no allocation) ----------------
__device__ ull      g_degp[N_NODES];                     // packed: cnt<<52 | wsum(32.32)
__device__ float    g_dinv[N_NODES];
__device__ __align__(16) float g_agg[N_NODES * C_DIM];   // 25.6 MB
__device__ __align__(8) int2 g_bkt[N_NODES * BCAP];      // 25.6 MB: (src, ew-bits)
__device__ int      g_ovfn;
__device__ __align__(16) int4 g_ovf[OVMAX];              // (src, ew-bits, dst, 0)
__device__ unsigned g_keys[N_NODES];
__device__ int      g_hist[NBUCK];
__device__ int      g_cnt;
__device__ int      g_thresh;
__device__ unsigned g_candk[CANDMAX];
__device__ int      g_candi[CANDMAX];
__device__ __align__(16) float g_Xt[C_DIM * C_DIM];
__device__ __align__(16) float g_gi[C_DIM * 3 * C_DIM];
__device__ __align__(16) float g_gh[C_DIM * 3 * C_DIM];
__device__ __align__(16) float g_Wnew[C_DIM * C_DIM];

// ---------------- side stream + events (created pre-main; no device memory) ----------------
struct HxSide {
    cudaStream_t s1;
    cudaEvent_t  evf, evj;
    HxSide() {
        cudaStreamCreateWithFlags(&s1, cudaStreamNonBlocking);
        cudaEventCreateWithFlags(&evf, cudaEventDisableTiming);
        cudaEventCreateWithFlags(&evj, cudaEventDisableTiming);
    }
};
static HxSide hx;

// ---------------- init ----------------
__global__ void k_init() {
    int i = blockIdx.x * blockDim.x + threadIdx.x;
    if (i < NBUCK)   g_hist[i] = 0;
    if (i < N_NODES) g_degp[i] = (1ull << 32);   // self-loop weight 1.0, count 0
    if (i == 0)      { g_cnt = 0; g_ovfn = 0; }
}

// ---------------- single edge pass: packed degree atomic gives bucket slot ----------------
__global__ void k_bucket(const int* __restrict__ ei, const float* __restrict__ ew) {
    int e = blockIdx.x * 256 + threadIdx.x;
    if (e >= E_EDGES) return;
    int src = ei[e];
    int dst = ei[E_EDGES + e];
    float w = ew[e];
    ull v = (ull)(w * 4294967296.0f) + (1ull << 52);
    ull old = atomicAdd(&g_degp[dst], v);
    int pos = (int)(old >> 52);
    if (pos < BCAP) {
        g_bkt[dst * BCAP + pos] = make_int2(src, __float_as_int(w));
    } else {
        int o = atomicAdd(&g_ovfn, 1);
        if (o < OVMAX) g_ovf[o] = make_int4(src, __float_as_int(w), dst, 0);
    }
}

// ---------------- dinv from packed weight sum ----------------
__global__ void k_dinv() {
    int i = blockIdx.x * 256 + threadIdx.x;
    if (i < N_NODES) {
        ull d = g_degp[i];
        float w = __ull2float_rn(d & ((1ull << 52) - 1ull)) * (1.0f / 4294967296.0f);
        g_dinv[i] = rsqrtf(w);                    // w >= 1 always
    }
}

// ---------------- atomic-free aggregation: warp per node, bucket walk ----------------
__global__ void k_agg(const float* __restrict__ X) {
    int gt   = blockIdx.x * blockDim.x + threadIdx.x;
    int w    = gt >> 5;
    int lane = gt & 31;
    if (w >= N_NODES) return;
    int cnt = (int)(g_degp[w] >> 52);
    if (cnt > BCAP) cnt = BCAP;
    float di = g_dinv[w];
    float4 x = ((const float4*)X)[w * 32 + lane];
    float4 acc = make_float4(x.x * di, x.y * di, x.z * di, x.w * di);  // self-loop: di*x
    const int2* row = g_bkt + w * BCAP;
    for (int e = 0; e < cnt; e++) {
        int2 c = row[e];                          // warp-uniform broadcast load
        float s = g_dinv[c.x] * __int_as_float(c.y);
        float4 xs = ((const float4*)X)[c.x * 32 + lane];
        acc.x += xs.x * s; acc.y += xs.y * s;
        acc.z += xs.z * s; acc.w += xs.w * s;
    }
    acc.x *= di; acc.y *= di; acc.z *= di; acc.w *= di;  // outer dinv[dst]
    ((float4*)g_agg)[w * 32 + lane] = acc;
}

// ---------------- overflow fixup (expected empty; correctness net) ----------------
__global__ void k_ovf(const float* __restrict__ X) {
    int n = g_ovfn; if (n > OVMAX) n = OVMAX;
    int gw   = (blockIdx.x * blockDim.x + threadIdx.x) >> 5;
    int lane = threadIdx.x & 31;
    int nw   = (gridDim.x * blockDim.x) >> 5;
    for (int i = gw; i < n; i += nw) {
        int4 c = g_ovf[i];
        float s = g_dinv[c.x] * __int_as_float(c.y) * g_dinv[c.z];
        float4 xs = ((const float4*)X)[c.x * 32 + lane];
        float* ptr = g_agg + c.z * C_DIM + lane * 4;
        asm volatile("red.global.add.v4.f32 [%0], {%1, %2, %3, %4};"
                     :: "l"(ptr), "f"(xs.x * s), "f"(xs.y * s), "f"(xs.z * s), "f"(xs.w * s)
                     : "memory");
    }
}

// ---------------- scores + key histogram (warp per node, pnorm fused) ----------------
__global__ void k_score(const float* __restrict__ X, const float* __restrict__ p) {
    __shared__ float4 ps[32];
    __shared__ float spinv;
    if (threadIdx.x < 32) {
        float4 q = ((const float4*)p)[threadIdx.x];
        ps[threadIdx.x] = q;
        float ss = q.x * q.x + q.y * q.y + q.z * q.z + q.w * q.w;
        #pragma unroll
        for (int o = 16; o; o >>= 1) ss += __shfl_xor_sync(0xffffffffu, ss, o);
        if (threadIdx.x == 0) spinv = rsqrtf(ss);
    }
    __syncthreads();
    int w    = (blockIdx.x * blockDim.x + threadIdx.x) >> 5;
    int lane = threadIdx.x & 31;
    if (w >= N_NODES) return;
    float4 x  = ((const float4*)X)[w * 32 + lane];
    float4 pp = ps[lane];
    float d = x.x * pp.x + x.y * pp.y + x.z * pp.z + x.w * pp.w;
    for (int o = 16; o; o >>= 1) d += __shfl_xor_sync(0xffffffffu, d, o);
    if (lane == 0) {
        float s = d * spinv;
        unsigned bits = __float_as_uint(s);
        unsigned key  = (bits & 0x80000000u) ? ~bits : (bits ^ 0x80000000u);
        g_keys[w] = key;
        atomicAdd(&g_hist[key >> 16], 1);
    }
}

// ---------------- threshold bucket ----------------
__global__ void k_thresh() {
    __shared__ int csum[1024];
    int t = threadIdx.x;
    int s = 0;
    int base = t * 64;
    for (int b = 0; b < 64; b++) s += g_hist[base + b];
    csum[t] = s;
    __syncthreads();
    if (t == 0) {
        int cum = 0, chunk = 0;
        for (int c = 1023; c >= 0; c--) {
            if (cum + csum[c] >= C_DIM) { chunk = c; break; }
            cum += csum[c];
        }
        int B = chunk * 64;
        for (int b = chunk * 64 + 63; b >= chunk * 64; b--) {
            cum += g_hist[b];
            if (cum >= C_DIM) { B = b; break; }
        }
        g_thresh = B;
    }
}

// ---------------- compact candidates ----------------
__global__ void k_compact() {
    int i = blockIdx.x * 256 + threadIdx.x;
    if (i >= N_NODES) return;
    unsigned key = g_keys[i];
    if ((int)(key >> 16) >= g_thresh) {
        int pos = atomicAdd(&g_cnt, 1);
        if (pos < CANDMAX) { g_candk[pos] = key; g_candi[pos] = i; }
    }
}

// ---------------- exact top-128 sort + X_tilde ----------------
__global__ void k_topk(const float* __restrict__ X) {
    __shared__ unsigned long long s[CANDMAX];
    __shared__ int   sidx[C_DIM];
    __shared__ float sgate[C_DIM];
    int t = threadIdx.x;
    int cnt = g_cnt; if (cnt > CANDMAX) cnt = CANDMAX;
    for (int i = t; i < CANDMAX; i += 256) {
        if (i < cnt)
            s[i] = ((unsigned long long)g_candk[i] << 32) |
                   (unsigned)(0xFFFFFFFFu - (unsigned)g_candi[i]);
        else
            s[i] = 0ull;
    }
    __syncthreads();
    for (int k2 = 2; k2 <= CANDMAX; k2 <<= 1)
        for (int j = k2 >> 1; j > 0; j >>= 1) {
            for (int i = t; i < CANDMAX; i += 256) {
                int ixj = i ^ j;
                if (ixj > i) {
                    unsigned long long a = s[i], b = s[ixj];
                    bool asc = ((i & k2) == 0);
                    if (asc ? (a > b) : (a < b)) { s[i] = b; s[ixj] = a; }
                }
            }
            __syncthreads();
        }
    if (t < C_DIM) {
        unsigned long long comp = s[CANDMAX - 1 - t];
        unsigned key = (unsigned)(comp >> 32);
        int idx = (int)(0xFFFFFFFFu - (unsigned)comp);
        unsigned bits = (key & 0x80000000u) ? (key ^ 0x80000000u) : ~key;
        sidx[t]  = idx;
        sgate[t] = tanhf(__uint_as_float(bits));
    }
    __syncthreads();
    for (int i = t; i < C_DIM * C_DIM; i += 256) {
        int r = i >> 7, c = i & 127;
        g_Xt[i] = X[sidx[r] * C_DIM + c] * sgate[r];
    }
}

// ---------------- merged GRU GEMMs: z=0: gi = Xt@W_ih^T ; z=1: gh = Wc@W_hh^T ----------------
__global__ void __launch_bounds__(256)
k_gemm(const float* __restrict__ Wc, const float* __restrict__ Wih,
       const float* __restrict__ Whh) {
    int mode = blockIdx.z;
    const float* A = (mode == 0) ? g_Xt : Wc;
    const float* B = (mode == 0) ? Wih  : Whh;
    float* Cm      = (mode == 0) ? g_gi : g_gh;
    const int Nn = 3 * C_DIM;

    extern __shared__ float sm[];
    float* Bs = sm;                 // [128][129]
    float* As = sm + 128 * 129;     // [64][128]
    int tid = threadIdx.x;
    int bx = blockIdx.x, by = blockIdx.y;

    #pragma unroll 4
    for (int it = 0; it < 64; it++) {
        int flat = tid + it * 256;
        int n = flat >> 7, k = flat & 127;
        Bs[n * 129 + k] = B[(by * 128 + n) * C_DIM + k];
    }
    int row0 = bx * 64;
    #pragma unroll 4
    for (int it = 0; it < 32; it++) {
        int flat = tid + it * 256;
        int r = flat >> 7, k = flat & 127;
        As[flat] = A[(row0 + r) * C_DIM + k];
    }
    __syncthreads();

    int tx = tid & 31, ty = tid >> 5;
    float acc[8][4];
    #pragma unroll
    for (int i = 0; i < 8; i++)
        #pragma unroll
        for (int j = 0; j < 4; j++) acc[i][j] = 0.0f;

    const float* Ap = As + ty * 8 * 128;
    const float* Bp = Bs + tx * 129;
    #pragma unroll 2
    for (int k4 = 0; k4 < 32; k4++) {
        float4 a4[8];
        #pragma unroll
        for (int i = 0; i < 8; i++)
            a4[i] = *(const float4*)(Ap + i * 128 + k4 * 4);
        #pragma unroll
        for (int j = 0; j < 4; j++) {
            const float* bp = Bp + j * (32 * 129) + k4 * 4;
            float b0 = bp[0], b1 = bp[1], b2 = bp[2], b3 = bp[3];
            #pragma unroll
            for (int i = 0; i < 8; i++)
                acc[i][j] += a4[i].x * b0 + a4[i].y * b1 + a4[i].z * b2 + a4[i].w * b3;
        }
    }
    #pragma unroll
    for (int i = 0; i < 8; i++) {
        int gr = row0 + ty * 8 + i;
        #pragma unroll
        for (int j = 0; j < 4; j++)
            Cm[gr * Nn + by * 128 + tx + 32 * j] = acc[i][j];
    }
}

// ---------------- GRU gates -> W_new ----------------
__global__ void k_gates(const float* __restrict__ b_ih, const float* __restrict__ b_hh,
                        const float* __restrict__ Wc) {
    int i = blockIdx.x * 256 + threadIdx.x;
    if (i >= C_DIM * C_DIM) return;
    int b = i >> 7, j = i & 127;
    float gir = g_gi[b * 384 + j]       + b_ih[j];
    float ghr = g_gh[b * 384 + j]       + b_hh[j];
    float giz = g_gi[b * 384 + 128 + j] + b_ih[128 + j];
    float ghz = g_gh[b * 384 + 128 + j] + b_hh[128 + j];
    float gin = g_gi[b * 384 + 256 + j] + b_ih[256 + j];
    float ghn = g_gh[b * 384 + 256 + j] + b_hh[256 + j];
    float r = 1.0f / (1.0f + expf(-(gir + ghr)));
    float z = 1.0f / (1.0f + expf(-(giz + ghz)));
    float n = tanhf(gin + r * ghn);
    g_Wnew[i] = (1.0f - z) * n + z * Wc[i];
}

// ---------------- final GEMM, BN=128 full-width, packed fma.rn.f32x2 ----------------
// out[m,n] = sum_k agg[m,k]*Wnew[n,k] + bias[n]
__global__ void __launch_bounds__(256, 2)
k_gemm2(float* __restrict__ out, const float* __restrict__ bias) {
    extern __shared__ float sm2[];
    float* Ast = sm2;                  // [128 k][68 m]
    float* Bst = sm2 + 128 * 68;       // [128 k][130 n]
    int tid = threadIdx.x;
    int row0 = blockIdx.x * 64;

    #pragma unroll 8
    for (int it = 0; it < 64; it++) {               // B: Wnew[n][k] -> Bst[k][n]
        int flat = tid + it * 256;
        int k = flat & 127, n = flat >> 7;
        Bst[k * 130 + n] = g_Wnew[n * C_DIM + k];
    }
    #pragma unroll 4
    for (int it = 0; it < 32; it++) {               // A: agg[row0+r][k] -> Ast[k][r]
        int flat = tid + it * 256;
        int k = flat & 127, r = flat >> 7;
        int gr = row0 + r;
        Ast[k * 68 + r] = (gr < N_NODES) ? g_agg[gr * C_DIM + k] : 0.0f;
    }
    __syncthreads();

    int tx = tid & 31, ty = tid >> 5;
    int m0 = ty * 8;
    ull acc[4][4];
    #pragma unroll
    for (int i = 0; i < 4; i++)
        #pragma unroll
        for (int j = 0; j < 4; j++) acc[i][j] = 0ull;

    #pragma unroll 2
    for (int k = 0; k < 128; k++) {
        double2 ad0 = *(const double2*)(Ast + k * 68 + m0);      // rows m0..m0+3
        double2 ad1 = *(const double2*)(Ast + k * 68 + m0 + 4);  // rows m0+4..m0+7
        ull a[4];
        a[0] = __double_as_longlong(ad0.x);
        a[1] = __double_as_longlong(ad0.y);
        a[2] = __double_as_longlong(ad1.x);
        a[3] = __double_as_longlong(ad1.y);
        ull bb[4];
        #pragma unroll
        for (int j = 0; j < 4; j++) {
            float b = Bst[k * 130 + tx + 32 * j];
            asm("mov.b64 %0, {%1, %1};" : "=l"(bb[j]) : "f"(b));
        }
        #pragma unroll
        for (int i = 0; i < 4; i++)
            #pragma unroll
            for (int j = 0; j < 4; j++)
                asm("fma.rn.f32x2 %0, %1, %2, %0;" : "+l"(acc[i][j]) : "l"(a[i]), "l"(bb[j]));
    }

    float bv[4];
    #pragma unroll
    for (int j = 0; j < 4; j++) bv[j] = bias[tx + 32 * j];
    #pragma unroll
    for (int i = 0; i < 4; i++) {
        int gr0 = row0 + m0 + 2 * i;
        int gr1 = gr0 + 1;
        #pragma unroll
        for (int j = 0; j < 4; j++) {
            float clo, chi;
            asm("mov.b64 {%0, %1}, %2;" : "=f"(clo), "=f"(chi) : "l"(acc[i][j]));
            if (gr0 < N_NODES) out[gr0 * C_DIM + tx + 32 * j] = clo + bv[j];
            if (gr1 < N_NODES) out[gr1 * C_DIM + tx + 32 * j] = chi + bv[j];
        }
    }
}

// ---------------- launch ----------------
extern "C" void kernel_launch(void* const* d_in, const int* in_sizes, int n_in,
                              void* d_out, int out_size) {
    const float* X      = (const float*)d_in[0];
    const float* ew     = (const float*)d_in[1];
    const float* p      = (const float*)d_in[2];
    const float* W_ih   = (const float*)d_in[3];
    const float* W_hh   = (const float*)d_in[4];
    const float* b_ih   = (const float*)d_in[5];
    const float* b_hh   = (const float*)d_in[6];
    const float* W_conv = (const float*)d_in[7];
    const float* b_conv = (const float*)d_in[8];
    const int*   ei     = (const int*)d_in[9];     // int32 (JAX x64 disabled)
    float* out = (float*)d_out;

    const int GEMM_SMEM  = (128 * 129 + 64 * 128) * sizeof(float);   // 98816 B
    const int GEMM2_SMEM = (128 * 68 + 128 * 130) * sizeof(float);   // 101376 B
    cudaFuncSetAttribute(k_gemm,  cudaFuncAttributeMaxDynamicSharedMemorySize, GEMM_SMEM);
    cudaFuncSetAttribute(k_gemm2, cudaFuncAttributeMaxDynamicSharedMemorySize, GEMM2_SMEM);

    // common init (hist zero + packed deg + counters)
    k_init<<<256, 256>>>();

    // ---- fork: chain B (topk/GRU) on side stream ----
    cudaEventRecord(hx.evf, 0);
    cudaStreamWaitEvent(hx.s1, hx.evf, 0);

    k_score  <<<(N_NODES + 7) / 8, 256, 0, hx.s1>>>(X, p);
    k_thresh <<<1, 1024, 0, hx.s1>>>();
    k_compact<<<(N_NODES + 255) / 256, 256, 0, hx.s1>>>();
    k_topk   <<<1, 256, 0, hx.s1>>>(X);
    k_gemm   <<<dim3(2, 3, 2), 256, GEMM_SMEM, hx.s1>>>(W_conv, W_ih, W_hh);
    k_gates  <<<64, 256, 0, hx.s1>>>(b_ih, b_hh, W_conv);
    cudaEventRecord(hx.evj, hx.s1);

    // ---- chain A (edge/agg) on main stream: bucket -> dinv -> agg -> ovf ----
    k_bucket<<<(E_EDGES + 255) / 256, 256>>>(ei, ew);
    k_dinv  <<<(N_NODES + 255) / 256, 256>>>();
    k_agg   <<<(N_NODES * 32 + 255) / 256, 256>>>(X);
    k_ovf   <<<8, 256>>>(X);

    // ---- join, then final GEMM ----
    cudaStreamWaitEvent(0, hx.evj, 0);
    k_gemm2<<<(N_NODES + 63) / 64, 256, GEMM2_SMEM>>>(out, b_conv);
}

// round 13
// speedup vs baseline: 1.1820x; 1.0552x over previous
#include <cuda_runtime.h>
#include <cstdint>

#define N_NODES 50000
#define C_DIM   128
#define E_EDGES 800000
#define NBUCK   65536
#define CANDMAX 2048
#define BCAP    64         // bucket capacity per node (E[deg]=16, P(>=64)~1e-18)
#define OVMAX   4096       // overflow safety net

typedef unsigned long long ull;

// ---------------- scratch (static device globals; no allocation) ----------------
__device__ ull      g_degp[N_NODES];                     // packed: cnt<<52 | wsum(32.32)
__device__ float    g_dinv[N_NODES];
__device__ __align__(16) float g_agg[N_NODES * C_DIM];   // 25.6 MB
__device__ __align__(8) int2 g_bkt[N_NODES * BCAP];      // 25.6 MB: (src, ew-bits)
__device__ int      g_ovfn;
__device__ __align__(16) int4 g_ovf[OVMAX];              // (src, ew-bits, dst, 0)
__device__ unsigned g_keys[N_NODES];
__device__ int      g_hist[NBUCK];
__device__ __align__(16) float g_Xt[C_DIM * C_DIM];
__device__ __align__(16) float g_gi[C_DIM * 3 * C_DIM];
__device__ __align__(16) float g_gh[C_DIM * 3 * C_DIM];
__device__ __align__(16) float g_Wnew[C_DIM * C_DIM];

// ---------------- side stream + events (created pre-main; no device memory) ----------------
struct HxSide {
    cudaStream_t s1;
    cudaEvent_t  evf, evj;
    HxSide() {
        cudaStreamCreateWithFlags(&s1, cudaStreamNonBlocking);
        cudaEventCreateWithFlags(&evf, cudaEventDisableTiming);
        cudaEventCreateWithFlags(&evj, cudaEventDisableTiming);
    }
};
static HxSide hx;

// ---------------- init A: packed degrees + overflow counter (main chain) ----------------
__global__ void k_initA() {
    int i = blockIdx.x * blockDim.x + threadIdx.x;
    if (i < N_NODES) g_degp[i] = (1ull << 32);   // self-loop weight 1.0, count 0
    if (i == 0)      g_ovfn = 0;
}

// ---------------- init B: histogram (side chain) ----------------
__global__ void k_initB() {
    int i = blockIdx.x * blockDim.x + threadIdx.x;
    if (i < NBUCK) g_hist[i] = 0;
}

// ---------------- single edge pass: packed degree atomic gives bucket slot ----------------
__global__ void k_bucket(const int* __restrict__ ei, const float* __restrict__ ew) {
    int e = blockIdx.x * 256 + threadIdx.x;
    if (e >= E_EDGES) return;
    int src = ei[e];
    int dst = ei[E_EDGES + e];
    float w = ew[e];
    ull v = (ull)(w * 4294967296.0f) + (1ull << 52);
    ull old = atomicAdd(&g_degp[dst], v);
    int pos = (int)(old >> 52);
    if (pos < BCAP) {
        g_bkt[dst * BCAP + pos] = make_int2(src, __float_as_int(w));
    } else {
        int o = atomicAdd(&g_ovfn, 1);
        if (o < OVMAX) g_ovf[o] = make_int4(src, __float_as_int(w), dst, 0);
    }
}

// ---------------- dinv from packed weight sum ----------------
__global__ void k_dinv() {
    int i = blockIdx.x * 256 + threadIdx.x;
    if (i < N_NODES) {
        ull d = g_degp[i];
        float w = __ull2float_rn(d & ((1ull << 52) - 1ull)) * (1.0f / 4294967296.0f);
        g_dinv[i] = rsqrtf(w);                    // w >= 1 always
    }
}

// ---------------- atomic-free aggregation: warp per node, bucket walk + inline overflow ----------------
__global__ void k_agg(const float* __restrict__ X) {
    int gt   = blockIdx.x * blockDim.x + threadIdx.x;
    int w    = gt >> 5;
    int lane = gt & 31;
    if (w >= N_NODES) return;
    int cnt = (int)(g_degp[w] >> 52);
    float di = g_dinv[w];
    float4 x = ((const float4*)X)[w * 32 + lane];
    float4 acc = make_float4(x.x * di, x.y * di, x.z * di, x.w * di);  // self-loop: di*x
    const int2* row = g_bkt + w * BCAP;
    int inb = (cnt < BCAP) ? cnt : BCAP;
    for (int e = 0; e < inb; e++) {
        int2 c = row[e];                          // warp-uniform broadcast load
        float s = g_dinv[c.x] * __int_as_float(c.y);
        float4 xs = ((const float4*)X)[c.x * 32 + lane];
        acc.x += xs.x * s; acc.y += xs.y * s;
        acc.z += xs.z * s; acc.w += xs.w * s;
    }
    if (cnt > BCAP) {                             // astronomically rare; exact fixup
        int n = g_ovfn; if (n > OVMAX) n = OVMAX;
        for (int i = 0; i < n; i++) {
            int4 c = g_ovf[i];
            if (c.z == w) {
                float s = g_dinv[c.x] * __int_as_float(c.y);
                float4 xs = ((const float4*)X)[c.x * 32 + lane];
                acc.x += xs.x * s; acc.y += xs.y * s;
                acc.z += xs.z * s; acc.w += xs.w * s;
            }
        }
    }
    acc.x *= di; acc.y *= di; acc.z *= di; acc.w *= di;  // outer dinv[dst]
    ((float4*)g_agg)[w * 32 + lane] = acc;
}

// ---------------- scores + key histogram (warp per node, pnorm fused) ----------------
__global__ void k_score(const float* __restrict__ X, const float* __restrict__ p) {
    __shared__ float4 ps[32];
    __shared__ float spinv;
    if (threadIdx.x < 32) {
        float4 q = ((const float4*)p)[threadIdx.x];
        ps[threadIdx.x] = q;
        float ss = q.x * q.x + q.y * q.y + q.z * q.z + q.w * q.w;
        #pragma unroll
        for (int o = 16; o; o >>= 1) ss += __shfl_xor_sync(0xffffffffu, ss, o);
        if (threadIdx.x == 0) spinv = rsqrtf(ss);
    }
    __syncthreads();
    int w    = (blockIdx.x * blockDim.x + threadIdx.x) >> 5;
    int lane = threadIdx.x & 31;
    if (w >= N_NODES) return;
    float4 x  = ((const float4*)X)[w * 32 + lane];
    float4 pp = ps[lane];
    float d = x.x * pp.x + x.y * pp.y + x.z * pp.z + x.w * pp.w;
    for (int o = 16; o; o >>= 1) d += __shfl_xor_sync(0xffffffffu, d, o);
    if (lane == 0) {
        float s = d * spinv;
        unsigned bits = __float_as_uint(s);
        unsigned key  = (bits & 0x80000000u) ? ~bits : (bits ^ 0x80000000u);
        g_keys[w] = key;
        atomicAdd(&g_hist[key >> 16], 1);
    }
}

// ---------------- fused select: thresh + compact + exact top-128 + X_tilde (1 block, 1024 thr) ----------------
__global__ void __launch_bounds__(1024)
k_select(const float* __restrict__ X) {
    __shared__ ull  s[CANDMAX];
    __shared__ int  csum[1024];
    __shared__ int  scnt;
    __shared__ int  sthresh;
    __shared__ int   sidx[C_DIM];
    __shared__ float sgate[C_DIM];
    int t = threadIdx.x;

    // --- phase 1: threshold bucket from histogram ---
    if (t == 0) scnt = 0;
    {
        int sum = 0, base = t * 64;
        #pragma unroll 8
        for (int b = 0; b < 64; b++) sum += g_hist[base + b];
        csum[t] = sum;
    }
    __syncthreads();
    if (t == 0) {
        int cum = 0, chunk = 0;
        for (int c = 1023; c >= 0; c--) {
            if (cum + csum[c] >= C_DIM) { chunk = c; break; }
            cum += csum[c];
        }
        int B = chunk * 64;
        for (int b = chunk * 64 + 63; b >= chunk * 64; b--) {
            cum += g_hist[b];
            if (cum >= C_DIM) { B = b; break; }
        }
        sthresh = B;
    }
    __syncthreads();
    int th = sthresh;

    // --- phase 2: compact candidates into smem ---
    for (int i = t; i < N_NODES; i += 1024) {
        unsigned key = g_keys[i];
        if ((int)(key >> 16) >= th) {
            int pos = atomicAdd(&scnt, 1);
            if (pos < CANDMAX)
                s[pos] = ((ull)key << 32) | (unsigned)(0xFFFFFFFFu - (unsigned)i);
        }
    }
    __syncthreads();
    int cnt = scnt; if (cnt > CANDMAX) cnt = CANDMAX;
    for (int i = t; i < CANDMAX; i += 1024)
        if (i >= cnt) s[i] = 0ull;
    __syncthreads();

    // --- phase 3: bitonic sort (2048, ascending) ---
    for (int k2 = 2; k2 <= CANDMAX; k2 <<= 1)
        for (int j = k2 >> 1; j > 0; j >>= 1) {
            for (int i = t; i < CANDMAX; i += 1024) {
                int ixj = i ^ j;
                if (ixj > i) {
                    ull a = s[i], b = s[ixj];
                    bool asc = ((i & k2) == 0);
                    if (asc ? (a > b) : (a < b)) { s[i] = b; s[ixj] = a; }
                }
            }
            __syncthreads();
        }

    // --- phase 4: extract top-128 (descending), gate, gather X_tilde ---
    if (t < C_DIM) {
        ull comp = s[CANDMAX - 1 - t];
        unsigned key = (unsigned)(comp >> 32);
        int idx = (int)(0xFFFFFFFFu - (unsigned)comp);
        unsigned bits = (key & 0x80000000u) ? (key ^ 0x80000000u) : ~key;
        sidx[t]  = idx;
        sgate[t] = tanhf(__uint_as_float(bits));
    }
    __syncthreads();
    for (int i = t; i < C_DIM * C_DIM; i += 1024) {
        int r = i >> 7, c = i & 127;
        g_Xt[i] = X[sidx[r] * C_DIM + c] * sgate[r];
    }
}

// ---------------- merged GRU GEMMs: z=0: gi = Xt@W_ih^T ; z=1: gh = Wc@W_hh^T ----------------
__global__ void __launch_bounds__(256)
k_gemm(const float* __restrict__ Wc, const float* __restrict__ Wih,
       const float* __restrict__ Whh) {
    int mode = blockIdx.z;
    const float* A = (mode == 0) ? g_Xt : Wc;
    const float* B = (mode == 0) ? Wih  : Whh;
    float* Cm      = (mode == 0) ? g_gi : g_gh;
    const int Nn = 3 * C_DIM;

    extern __shared__ float sm[];
    float* Bs = sm;                 // [128][129]
    float* As = sm + 128 * 129;     // [64][128]
    int tid = threadIdx.x;
    int bx = blockIdx.x, by = blockIdx.y;

    #pragma unroll 4
    for (int it = 0; it < 64; it++) {
        int flat = tid + it * 256;
        int n = flat >> 7, k = flat & 127;
        Bs[n * 129 + k] = B[(by * 128 + n) * C_DIM + k];
    }
    int row0 = bx * 64;
    #pragma unroll 4
    for (int it = 0; it < 32; it++) {
        int flat = tid + it * 256;
        int r = flat >> 7, k = flat & 127;
        As[flat] = A[(row0 + r) * C_DIM + k];
    }
    __syncthreads();

    int tx = tid & 31, ty = tid >> 5;
    float acc[8][4];
    #pragma unroll
    for (int i = 0; i < 8; i++)
        #pragma unroll
        for (int j = 0; j < 4; j++) acc[i][j] = 0.0f;

    const float* Ap = As + ty * 8 * 128;
    const float* Bp = Bs + tx * 129;
    #pragma unroll 2
    for (int k4 = 0; k4 < 32; k4++) {
        float4 a4[8];
        #pragma unroll
        for (int i = 0; i < 8; i++)
            a4[i] = *(const float4*)(Ap + i * 128 + k4 * 4);
        #pragma unroll
        for (int j = 0; j < 4; j++) {
            const float* bp = Bp + j * (32 * 129) + k4 * 4;
            float b0 = bp[0], b1 = bp[1], b2 = bp[2], b3 = bp[3];
            #pragma unroll
            for (int i = 0; i < 8; i++)
                acc[i][j] += a4[i].x * b0 + a4[i].y * b1 + a4[i].z * b2 + a4[i].w * b3;
        }
    }
    #pragma unroll
    for (int i = 0; i < 8; i++) {
        int gr = row0 + ty * 8 + i;
        #pragma unroll
        for (int j = 0; j < 4; j++)
            Cm[gr * Nn + by * 128 + tx + 32 * j] = acc[i][j];
    }
}

// ---------------- GRU gates -> W_new ----------------
__global__ void k_gates(const float* __restrict__ b_ih, const float* __restrict__ b_hh,
                        const float* __restrict__ Wc) {
    int i = blockIdx.x * 256 + threadIdx.x;
    if (i >= C_DIM * C_DIM) return;
    int b = i >> 7, j = i & 127;
    float gir = g_gi[b * 384 + j]       + b_ih[j];
    float ghr = g_gh[b * 384 + j]       + b_hh[j];
    float giz = g_gi[b * 384 + 128 + j] + b_ih[128 + j];
    float ghz = g_gh[b * 384 + 128 + j] + b_hh[128 + j];
    float gin = g_gi[b * 384 + 256 + j] + b_ih[256 + j];
    float ghn = g_gh[b * 384 + 256 + j] + b_hh[256 + j];
    float r = 1.0f / (1.0f + expf(-(gir + ghr)));
    float z = 1.0f / (1.0f + expf(-(giz + ghz)));
    float n = tanhf(gin + r * ghn);
    g_Wnew[i] = (1.0f - z) * n + z * Wc[i];
}

// ---------------- final GEMM, BN=128 full-width, packed fma.rn.f32x2 ----------------
// out[m,n] = sum_k agg[m,k]*Wnew[n,k] + bias[n]
__global__ void __launch_bounds__(256, 2)
k_gemm2(float* __restrict__ out, const float* __restrict__ bias) {
    extern __shared__ float sm2[];
    float* Ast = sm2;                  // [128 k][68 m]
    float* Bst = sm2 + 128 * 68;       // [128 k][130 n]
    int tid = threadIdx.x;
    int row0 = blockIdx.x * 64;

    #pragma unroll 8
    for (int it = 0; it < 64; it++) {               // B: Wnew[n][k] -> Bst[k][n]
        int flat = tid + it * 256;
        int k = flat & 127, n = flat >> 7;
        Bst[k * 130 + n] = g_Wnew[n * C_DIM + k];
    }
    #pragma unroll 4
    for (int it = 0; it < 32; it++) {               // A: agg[row0+r][k] -> Ast[k][r]
        int flat = tid + it * 256;
        int k = flat & 127, r = flat >> 7;
        int gr = row0 + r;
        Ast[k * 68 + r] = (gr < N_NODES) ? g_agg[gr * C_DIM + k] : 0.0f;
    }
    __syncthreads();

    int tx = tid & 31, ty = tid >> 5;
    int m0 = ty * 8;
    ull acc[4][4];
    #pragma unroll
    for (int i = 0; i < 4; i++)
        #pragma unroll
        for (int j = 0; j < 4; j++) acc[i][j] = 0ull;

    #pragma unroll 2
    for (int k = 0; k < 128; k++) {
        double2 ad0 = *(const double2*)(Ast + k * 68 + m0);      // rows m0..m0+3
        double2 ad1 = *(const double2*)(Ast + k * 68 + m0 + 4);  // rows m0+4..m0+7
        ull a[4];
        a[0] = __double_as_longlong(ad0.x);
        a[1] = __double_as_longlong(ad0.y);
        a[2] = __double_as_longlong(ad1.x);
        a[3] = __double_as_longlong(ad1.y);
        ull bb[4];
        #pragma unroll
        for (int j = 0; j < 4; j++) {
            float b = Bst[k * 130 + tx + 32 * j];
            asm("mov.b64 %0, {%1, %1};" : "=l"(bb[j]) : "f"(b));
        }
        #pragma unroll
        for (int i = 0; i < 4; i++)
            #pragma unroll
            for (int j = 0; j < 4; j++)
                asm("fma.rn.f32x2 %0, %1, %2, %0;" : "+l"(acc[i][j]) : "l"(a[i]), "l"(bb[j]));
    }

    float bv[4];
    #pragma unroll
    for (int j = 0; j < 4; j++) bv[j] = bias[tx + 32 * j];
    #pragma unroll
    for (int i = 0; i < 4; i++) {
        int gr0 = row0 + m0 + 2 * i;
        int gr1 = gr0 + 1;
        #pragma unroll
        for (int j = 0; j < 4; j++) {
            float clo, chi;
            asm("mov.b64 {%0, %1}, %2;" : "=f"(clo), "=f"(chi) : "l"(acc[i][j]));
            if (gr0 < N_NODES) out[gr0 * C_DIM + tx + 32 * j] = clo + bv[j];
            if (gr1 < N_NODES) out[gr1 * C_DIM + tx + 32 * j] = chi + bv[j];
        }
    }
}

// ---------------- launch ----------------
extern "C" void kernel_launch(void* const* d_in, const int* in_sizes, int n_in,
                              void* d_out, int out_size) {
    const float* X      = (const float*)d_in[0];
    const float* ew     = (const float*)d_in[1];
    const float* p      = (const float*)d_in[2];
    const float* W_ih   = (const float*)d_in[3];
    const float* W_hh   = (const float*)d_in[4];
    const float* b_ih   = (const float*)d_in[5];
    const float* b_hh   = (const float*)d_in[6];
    const float* W_conv = (const float*)d_in[7];
    const float* b_conv = (const float*)d_in[8];
    const int*   ei     = (const int*)d_in[9];     // int32 (JAX x64 disabled)
    float* out = (float*)d_out;

    const int GEMM_SMEM  = (128 * 129 + 64 * 128) * sizeof(float);   // 98816 B
    const int GEMM2_SMEM = (128 * 68 + 128 * 130) * sizeof(float);   // 101376 B
    cudaFuncSetAttribute(k_gemm,  cudaFuncAttributeMaxDynamicSharedMemorySize, GEMM_SMEM);
    cudaFuncSetAttribute(k_gemm2, cudaFuncAttributeMaxDynamicSharedMemorySize, GEMM2_SMEM);

    // ---- fork at t=0: chain B (topk/GRU) on side stream ----
    cudaEventRecord(hx.evf, 0);
    cudaStreamWaitEvent(hx.s1, hx.evf, 0);

    k_initB <<<256, 256, 0, hx.s1>>>();
    k_score <<<(N_NODES + 7) / 8, 256, 0, hx.s1>>>(X, p);
    k_select<<<1, 1024, 0, hx.s1>>>(X);
    k_gemm  <<<dim3(2, 3, 2), 256, GEMM_SMEM, hx.s1>>>(W_conv, W_ih, W_hh);
    k_gates <<<64, 256, 0, hx.s1>>>(b_ih, b_hh, W_conv);
    cudaEventRecord(hx.evj, hx.s1);

    // ---- chain A (edge/agg) on main stream: initA -> bucket -> dinv -> agg ----
    k_initA <<<(N_NODES + 255) / 256, 256>>>();
    k_bucket<<<(E_EDGES + 255) / 256, 256>>>(ei, ew);
    k_dinv  <<<(N_NODES + 255) / 256, 256>>>();
    k_agg   <<<(N_NODES * 32 + 255) / 256, 256>>>(X);

    // ---- join, then final GEMM ----
    cudaStreamWaitEvent(0, hx.evj, 0);
    k_gemm2<<<(N_NODES + 63) / 64, 256, GEMM2_SMEM>>>(out, b_conv);
}